// round 8
// baseline (speedup 1.0000x reference)
#include <cuda_runtime.h>
#include <math.h>

#define NN  100000
#define NE  6400000
#define IND 128
#define NB1MAX 128   // max scan blocks (ceil(100000/1024)=98)

// ---------------- static device scratch (no runtime allocation) ----------------
static __device__ int   g_is64;
static __device__ int   g_cnt[NN];        // in-degree (edge count) per node
static __device__ int   g_rowstart[NN];   // exclusive prefix of g_cnt
static __device__ int   g_cursor[NN];     // placement tickets
static __device__ int   g_blksum[NB1MAX];
static __device__ int   g_blkoff[NB1MAX];
static __device__ float g_dis[NN];        // deg^{-1/2}
static __device__ __align__(16) float g_h1[NN * 16];  // layer-1 h' (12 used, 64B stride)
static __device__ __align__(16) float g_h2[NN * 8];   // layer-2 h' (6 used, 32B stride)
static __device__ __align__(16) float g_h3[NN * 4];   // layer-3 h' (3 used, 16B stride)
static __device__ __align__(16) int2  g_csr[NE];      // (src, weight-bits) grouped by dst

// ---------------- dtype detection: int64 edge_index has zero high words ----------------
__global__ void k_detect(const unsigned int* __restrict__ p) {
    if (threadIdx.x == 0 && blockIdx.x == 0) {
        int is64 = 1;
        #pragma unroll
        for (int j = 0; j < 16; j++)
            if (p[2 * j + 1] != 0u) is64 = 0;
        g_is64 = is64;
    }
}

__global__ void k_zero(int n) {
    int i = blockIdx.x * blockDim.x + threadIdx.x;
    if (i < n) g_cnt[i] = 0;
}

// count edges per destination (reads dst row of edge_index only)
__global__ void k_count(const void* __restrict__ eiv, int E) {
    int e = blockIdx.x * blockDim.x + threadIdx.x;
    if (e >= E) return;
    int d;
    if (g_is64) d = (int)((const long long*)eiv)[(long long)E + e];
    else        d = ((const int*)eiv)[E + e];
    atomicAdd(&g_cnt[d], 1);
}

// ---------------- 3-kernel exclusive scan of g_cnt -> g_rowstart ----------------
__global__ void k_scan1(int n) {
    __shared__ int ss[256];
    int tid = threadIdx.x;
    int base = blockIdx.x * 1024 + tid * 4;
    int c0 = (base + 0 < n) ? g_cnt[base + 0] : 0;
    int c1 = (base + 1 < n) ? g_cnt[base + 1] : 0;
    int c2 = (base + 2 < n) ? g_cnt[base + 2] : 0;
    int c3 = (base + 3 < n) ? g_cnt[base + 3] : 0;
    int s = c0 + c1 + c2 + c3;
    ss[tid] = s;
    __syncthreads();
    #pragma unroll
    for (int off = 1; off < 256; off <<= 1) {
        int v = (tid >= off) ? ss[tid - off] : 0;
        __syncthreads();
        ss[tid] += v;
        __syncthreads();
    }
    int excl = ss[tid] - s;
    if (tid == 255) g_blksum[blockIdx.x] = ss[255];
    int r = excl;
    if (base + 0 < n) g_rowstart[base + 0] = r; r += c0;
    if (base + 1 < n) g_rowstart[base + 1] = r; r += c1;
    if (base + 2 < n) g_rowstart[base + 2] = r; r += c2;
    if (base + 3 < n) g_rowstart[base + 3] = r;
}

__global__ void k_scan2(int nb1) {
    __shared__ int ss[128];
    int tid = threadIdx.x;
    int v = (tid < nb1) ? g_blksum[tid] : 0;
    ss[tid] = v;
    __syncthreads();
    #pragma unroll
    for (int off = 1; off < 128; off <<= 1) {
        int u = (tid >= off) ? ss[tid - off] : 0;
        __syncthreads();
        ss[tid] += u;
        __syncthreads();
    }
    if (tid < nb1) g_blkoff[tid] = ss[tid] - v;
}

__global__ void k_scan3(int n) {
    int i = blockIdx.x * blockDim.x + threadIdx.x;
    if (i >= n) return;
    int r = g_rowstart[i] + g_blkoff[i >> 10];
    g_rowstart[i] = r;
    g_cursor[i]   = r;
}

// ---------------- CSR placement: (src, w) grouped by dst ----------------
__global__ void k_place(const void* __restrict__ eiv, const float* __restrict__ ew, int E) {
    int e = blockIdx.x * blockDim.x + threadIdx.x;
    if (e >= E) return;
    int s, d;
    if (g_is64) {
        const long long* ei = (const long long*)eiv;
        s = (int)ei[e];
        d = (int)ei[(long long)E + e];
    } else {
        const int* ei = (const int*)eiv;
        s = ei[e];
        d = ei[E + e];
    }
    float w = ew[e];
    int pos = atomicAdd(&g_cursor[d], 1);
    g_csr[pos] = make_int2(s, __float_as_int(w));
}

// ---------------- warp shuffle reduce helper ----------------
__device__ __forceinline__ float wred(float v) {
    #pragma unroll
    for (int o = 16; o; o >>= 1) v += __shfl_down_sync(0xffffffffu, v, o);
    return v;
}

// ---------------- weighted degree -> dis = rsqrt(1 + sum w) ----------------
__global__ void __launch_bounds__(256) k_deg(int n) {
    int gid  = blockIdx.x * blockDim.x + threadIdx.x;
    int node = gid >> 5, lane = gid & 31;
    if (node >= n) return;
    int beg = g_rowstart[node], cnt = g_cnt[node];
    float s = 0.0f;
    for (int j = lane; j < cnt; j += 32)
        s += __int_as_float(g_csr[beg + j].y);
    s = wred(s);
    if (lane == 0) g_dis[node] = rsqrtf(1.0f + s);  // self-loop weight 1
}

// ---------------- layer 1 matmul: h1' = dis * (X @ W1), 64B row stride ----------------
__global__ void __launch_bounds__(128) k_mm1(const float* __restrict__ X,
                                             const float* __restrict__ W1, int n) {
    __shared__ float sW[IND * 12];
    for (int i = threadIdx.x; i < IND * 12; i += blockDim.x) sW[i] = W1[i];
    __syncthreads();
    int i = blockIdx.x * blockDim.x + threadIdx.x;
    if (i >= n) return;
    float acc[12];
    #pragma unroll
    for (int d = 0; d < 12; d++) acc[d] = 0.0f;
    const float4* xr = reinterpret_cast<const float4*>(X + (size_t)i * IND);
    #pragma unroll
    for (int k4 = 0; k4 < IND / 4; k4++) {
        float4 v = xr[k4];
        const float* w = &sW[k4 * 48];
        #pragma unroll
        for (int d = 0; d < 12; d++)
            acc[d] += v.x * w[d] + v.y * w[12 + d] + v.z * w[24 + d] + v.w * w[36 + d];
    }
    float di = g_dis[i];
    float4* hO = reinterpret_cast<float4*>(g_h1 + (size_t)i * 16);
    #pragma unroll
    for (int q = 0; q < 3; q++)
        hO[q] = make_float4(di * acc[q*4+0], di * acc[q*4+1], di * acc[q*4+2], di * acc[q*4+3]);
}

// ---------------- layer-1 gather (+ fused relu + mm2): warp per node ----------------
__global__ void __launch_bounds__(256) k_gat1(const float* __restrict__ b1,
                                              const float* __restrict__ W2, int n) {
    int gid  = blockIdx.x * blockDim.x + threadIdx.x;
    int node = gid >> 5, lane = gid & 31;
    if (node >= n) return;
    int beg = g_rowstart[node], cnt = g_cnt[node];
    float acc[12];
    #pragma unroll
    for (int d = 0; d < 12; d++) acc[d] = 0.0f;
    for (int j = lane; j < cnt; j += 32) {
        int2 e = g_csr[beg + j];
        float w = __int_as_float(e.y);
        const float4* hs = reinterpret_cast<const float4*>(g_h1 + (size_t)e.x * 16);
        float4 a = hs[0], b = hs[1], c = hs[2];
        acc[0] += w * a.x;  acc[1] += w * a.y;  acc[2]  += w * a.z;  acc[3]  += w * a.w;
        acc[4] += w * b.x;  acc[5] += w * b.y;  acc[6]  += w * b.z;  acc[7]  += w * b.w;
        acc[8] += w * c.x;  acc[9] += w * c.y;  acc[10] += w * c.z;  acc[11] += w * c.w;
    }
    #pragma unroll
    for (int d = 0; d < 12; d++) acc[d] = wred(acc[d]);
    if (lane == 0) {
        float di = g_dis[node];
        const float* self = g_h1 + (size_t)node * 16;
        float o[6];
        #pragma unroll
        for (int d = 0; d < 6; d++) o[d] = 0.0f;
        #pragma unroll
        for (int k = 0; k < 12; k++) {
            float xv = fmaxf(fmaf(di, acc[k] + self[k], __ldg(&b1[k])), 0.0f);
            #pragma unroll
            for (int d = 0; d < 6; d++)
                o[d] = fmaf(xv, __ldg(&W2[k * 6 + d]), o[d]);
        }
        float4* hO = reinterpret_cast<float4*>(g_h2 + (size_t)node * 8);
        hO[0] = make_float4(di * o[0], di * o[1], di * o[2], di * o[3]);
        hO[1] = make_float4(di * o[4], di * o[5], 0.0f, 0.0f);
    }
}

// ---------------- layer-2 gather (+ fused relu + mm3) ----------------
__global__ void __launch_bounds__(256) k_gat2(const float* __restrict__ b2,
                                              const float* __restrict__ W3, int n) {
    int gid  = blockIdx.x * blockDim.x + threadIdx.x;
    int node = gid >> 5, lane = gid & 31;
    if (node >= n) return;
    int beg = g_rowstart[node], cnt = g_cnt[node];
    float acc[6];
    #pragma unroll
    for (int d = 0; d < 6; d++) acc[d] = 0.0f;
    for (int j = lane; j < cnt; j += 32) {
        int2 e = g_csr[beg + j];
        float w = __int_as_float(e.y);
        const float4* hs = reinterpret_cast<const float4*>(g_h2 + (size_t)e.x * 8);
        float4 a = hs[0], b = hs[1];
        acc[0] += w * a.x;  acc[1] += w * a.y;  acc[2] += w * a.z;
        acc[3] += w * a.w;  acc[4] += w * b.x;  acc[5] += w * b.y;
    }
    #pragma unroll
    for (int d = 0; d < 6; d++) acc[d] = wred(acc[d]);
    if (lane == 0) {
        float di = g_dis[node];
        const float* self = g_h2 + (size_t)node * 8;
        float o[3] = {0.0f, 0.0f, 0.0f};
        #pragma unroll
        for (int k = 0; k < 6; k++) {
            float xv = fmaxf(fmaf(di, acc[k] + self[k], __ldg(&b2[k])), 0.0f);
            #pragma unroll
            for (int d = 0; d < 3; d++)
                o[d] = fmaf(xv, __ldg(&W3[k * 3 + d]), o[d]);
        }
        *reinterpret_cast<float4*>(g_h3 + (size_t)node * 4) =
            make_float4(di * o[0], di * o[1], di * o[2], 0.0f);
    }
}

// ---------------- layer-3 gather (+ fused relu + linear + sigmoid) ----------------
__global__ void __launch_bounds__(256) k_gat3(const float* __restrict__ b3,
                                              const float* __restrict__ Wl,
                                              const float* __restrict__ bl,
                                              float* __restrict__ out, int n) {
    int gid  = blockIdx.x * blockDim.x + threadIdx.x;
    int node = gid >> 5, lane = gid & 31;
    if (node >= n) return;
    int beg = g_rowstart[node], cnt = g_cnt[node];
    float a0 = 0.0f, a1 = 0.0f, a2 = 0.0f;
    for (int j = lane; j < cnt; j += 32) {
        int2 e = g_csr[beg + j];
        float w = __int_as_float(e.y);
        float4 h = *reinterpret_cast<const float4*>(g_h3 + (size_t)e.x * 4);
        a0 += w * h.x;  a1 += w * h.y;  a2 += w * h.z;
    }
    a0 = wred(a0);  a1 = wred(a1);  a2 = wred(a2);
    if (lane == 0) {
        float di = g_dis[node];
        const float* self = g_h3 + (size_t)node * 4;
        float v0 = fmaxf(fmaf(di, a0 + self[0], __ldg(&b3[0])), 0.0f);
        float v1 = fmaxf(fmaf(di, a1 + self[1], __ldg(&b3[1])), 0.0f);
        float v2 = fmaxf(fmaf(di, a2 + self[2], __ldg(&b3[2])), 0.0f);
        float z = __ldg(&bl[0]);
        z = fmaf(v0, __ldg(&Wl[0]), z);
        z = fmaf(v1, __ldg(&Wl[1]), z);
        z = fmaf(v2, __ldg(&Wl[2]), z);
        out[node] = 1.0f / (1.0f + expf(-z));
    }
}

// ---------------- launcher ----------------
extern "C" void kernel_launch(void* const* d_in, const int* in_sizes, int n_in,
                              void* d_out, int out_size) {
    const float* X  = (const float*)d_in[0];
    const void*  EI = d_in[1];
    const float* EW = (const float*)d_in[2];
    const float* W1 = (const float*)d_in[3];
    const float* B1 = (const float*)d_in[4];
    const float* W2 = (const float*)d_in[5];
    const float* B2 = (const float*)d_in[6];
    const float* W3 = (const float*)d_in[7];
    const float* B3 = (const float*)d_in[8];
    const float* WL = (const float*)d_in[9];
    const float* BL = (const float*)d_in[10];

    int n = in_sizes[0] / IND;
    if (n > NN) n = NN;
    int E = in_sizes[2];
    if (E > NE) E = NE;

    int nb   = (n + 255) / 256;
    int eb   = (E + 255) / 256;
    int nb1  = (n + 1023) / 1024;           // scan blocks
    int wb   = ((n * 32) + 255) / 256;      // warp-per-node blocks

    k_detect<<<1, 32>>>((const unsigned int*)EI);
    k_zero  <<<nb, 256>>>(n);
    k_count <<<eb, 256>>>(EI, E);
    k_scan1 <<<nb1, 256>>>(n);
    k_scan2 <<<1, 128>>>(nb1);
    k_scan3 <<<nb, 256>>>(n);
    k_place <<<eb, 256>>>(EI, EW, E);

    k_deg   <<<wb, 256>>>(n);
    k_mm1   <<<(n + 127) / 128, 128>>>(X, W1, n);
    k_gat1  <<<wb, 256>>>(B1, W2, n);
    k_gat2  <<<wb, 256>>>(B2, W3, n);
    k_gat3  <<<wb, 256>>>(B3, WL, BL, (float*)d_out, n);
}

// round 9
// speedup vs baseline: 1.1819x; 1.1819x over previous
#include <cuda_runtime.h>
#include <math.h>

#define NN  100000
#define NE  6400000
#define IND 128
#define NB1MAX 128   // max scan blocks (ceil(100000/1024)=98)

// ---------------- static device scratch (no runtime allocation) ----------------
static __device__ int   g_is64;
static __device__ int   g_cnt[NN];        // in-degree (edge count) per node
static __device__ int   g_rowstart[NN];   // exclusive prefix of g_cnt
static __device__ int   g_cursor[NN];     // placement tickets
static __device__ int   g_blksum[NB1MAX];
static __device__ int   g_blkoff[NB1MAX];
static __device__ float g_deg[NN];        // 1 + sum of incident weights
static __device__ float g_dis[NN];        // deg^{-1/2}
static __device__ __align__(16) float g_h1[NN * 16];  // layer-1 h' (12 used, 64B stride)
static __device__ __align__(16) float g_h2[NN * 8];   // layer-2 h' (6 used, 32B stride)
static __device__ __align__(16) float g_h3[NN * 4];   // layer-3 h' (3 used, 16B stride)
static __device__ __align__(16) int2  g_csr[NE];      // (src, weight-bits) grouped by dst

// ---------------- helpers ----------------
__device__ __forceinline__ void red1(float* p, float a) {
    asm volatile("red.global.add.f32 [%0], %1;" :: "l"(p), "f"(a) : "memory");
}
// 8-lane xor-tree reduce (lanes grouped 0-7, 8-15, ...)
__device__ __forceinline__ float r8(float v) {
    v += __shfl_xor_sync(0xffffffffu, v, 4);
    v += __shfl_xor_sync(0xffffffffu, v, 2);
    v += __shfl_xor_sync(0xffffffffu, v, 1);
    return v;
}

// ---------------- dtype detection: int64 edge_index has zero high words ----------------
__global__ void k_detect(const unsigned int* __restrict__ p) {
    if (threadIdx.x == 0 && blockIdx.x == 0) {
        int is64 = 1;
        #pragma unroll
        for (int j = 0; j < 16; j++)
            if (p[2 * j + 1] != 0u) is64 = 0;
        g_is64 = is64;
    }
}

__global__ void k_zero(int n) {
    int i = blockIdx.x * blockDim.x + threadIdx.x;
    if (i < n) { g_cnt[i] = 0; g_deg[i] = 1.0f; }  // self-loop weight 1
}

// count edges per destination (reads dst row of edge_index only), 4 edges/thread
__global__ void k_count(const void* __restrict__ eiv, int E) {
    int e0 = (blockIdx.x * blockDim.x + threadIdx.x) * 4;
    if (e0 >= E) return;
    if (g_is64) {
        const long long* base = (const long long*)eiv + E;
        if (e0 + 4 <= E) {
            longlong2 a = *(const longlong2*)(base + e0);
            longlong2 b = *(const longlong2*)(base + e0 + 2);
            atomicAdd(&g_cnt[(int)a.x], 1);
            atomicAdd(&g_cnt[(int)a.y], 1);
            atomicAdd(&g_cnt[(int)b.x], 1);
            atomicAdd(&g_cnt[(int)b.y], 1);
        } else {
            for (int e = e0; e < E; e++) atomicAdd(&g_cnt[(int)base[e]], 1);
        }
    } else {
        const int* base = (const int*)eiv + E;
        if (e0 + 4 <= E) {
            int4 a = *(const int4*)(base + e0);
            atomicAdd(&g_cnt[a.x], 1);
            atomicAdd(&g_cnt[a.y], 1);
            atomicAdd(&g_cnt[a.z], 1);
            atomicAdd(&g_cnt[a.w], 1);
        } else {
            for (int e = e0; e < E; e++) atomicAdd(&g_cnt[base[e]], 1);
        }
    }
}

// ---------------- 3-kernel exclusive scan of g_cnt -> g_rowstart ----------------
__global__ void k_scan1(int n) {
    __shared__ int ss[256];
    int tid = threadIdx.x;
    int base = blockIdx.x * 1024 + tid * 4;
    int c0 = (base + 0 < n) ? g_cnt[base + 0] : 0;
    int c1 = (base + 1 < n) ? g_cnt[base + 1] : 0;
    int c2 = (base + 2 < n) ? g_cnt[base + 2] : 0;
    int c3 = (base + 3 < n) ? g_cnt[base + 3] : 0;
    int s = c0 + c1 + c2 + c3;
    ss[tid] = s;
    __syncthreads();
    #pragma unroll
    for (int off = 1; off < 256; off <<= 1) {
        int v = (tid >= off) ? ss[tid - off] : 0;
        __syncthreads();
        ss[tid] += v;
        __syncthreads();
    }
    int excl = ss[tid] - s;
    if (tid == 255) g_blksum[blockIdx.x] = ss[255];
    int r = excl;
    if (base + 0 < n) g_rowstart[base + 0] = r; r += c0;
    if (base + 1 < n) g_rowstart[base + 1] = r; r += c1;
    if (base + 2 < n) g_rowstart[base + 2] = r; r += c2;
    if (base + 3 < n) g_rowstart[base + 3] = r;
}

__global__ void k_scan2(int nb1) {
    __shared__ int ss[128];
    int tid = threadIdx.x;
    int v = (tid < nb1) ? g_blksum[tid] : 0;
    ss[tid] = v;
    __syncthreads();
    #pragma unroll
    for (int off = 1; off < 128; off <<= 1) {
        int u = (tid >= off) ? ss[tid - off] : 0;
        __syncthreads();
        ss[tid] += u;
        __syncthreads();
    }
    if (tid < nb1) g_blkoff[tid] = ss[tid] - v;
}

__global__ void k_scan3(int n) {
    int i = blockIdx.x * blockDim.x + threadIdx.x;
    if (i >= n) return;
    int r = g_rowstart[i] + g_blkoff[i >> 10];
    g_rowstart[i] = r;
    g_cursor[i]   = r;
}

// ---------------- CSR placement (4 edges/thread) + fused weighted-degree REDs ----------------
__device__ __forceinline__ void place1(int s, int d, float w) {
    int pos = atomicAdd(&g_cursor[d], 1);
    g_csr[pos] = make_int2(s, __float_as_int(w));
    red1(&g_deg[d], w);
}
__global__ void k_place(const void* __restrict__ eiv, const float* __restrict__ ew, int E) {
    int e0 = (blockIdx.x * blockDim.x + threadIdx.x) * 4;
    if (e0 >= E) return;
    if (g_is64) {
        const long long* sb = (const long long*)eiv;
        const long long* db = sb + E;
        if (e0 + 4 <= E) {
            longlong2 s01 = *(const longlong2*)(sb + e0);
            longlong2 s23 = *(const longlong2*)(sb + e0 + 2);
            longlong2 d01 = *(const longlong2*)(db + e0);
            longlong2 d23 = *(const longlong2*)(db + e0 + 2);
            float4 w4 = *(const float4*)(ew + e0);
            place1((int)s01.x, (int)d01.x, w4.x);
            place1((int)s01.y, (int)d01.y, w4.y);
            place1((int)s23.x, (int)d23.x, w4.z);
            place1((int)s23.y, (int)d23.y, w4.w);
        } else {
            for (int e = e0; e < E; e++) place1((int)sb[e], (int)db[e], ew[e]);
        }
    } else {
        const int* sb = (const int*)eiv;
        const int* db = sb + E;
        if (e0 + 4 <= E) {
            int4 s4 = *(const int4*)(sb + e0);
            int4 d4 = *(const int4*)(db + e0);
            float4 w4 = *(const float4*)(ew + e0);
            place1(s4.x, d4.x, w4.x);
            place1(s4.y, d4.y, w4.y);
            place1(s4.z, d4.z, w4.z);
            place1(s4.w, d4.w, w4.w);
        } else {
            for (int e = e0; e < E; e++) place1(sb[e], db[e], ew[e]);
        }
    }
}

__global__ void k_dis(int n) {
    int i = blockIdx.x * blockDim.x + threadIdx.x;
    if (i < n) g_dis[i] = rsqrtf(g_deg[i]);
}

// ---------------- layer 1 matmul: h1' = dis * (X @ W1), 64B row stride ----------------
__global__ void __launch_bounds__(128) k_mm1(const float* __restrict__ X,
                                             const float* __restrict__ W1, int n) {
    __shared__ float sW[IND * 12];
    for (int i = threadIdx.x; i < IND * 12; i += blockDim.x) sW[i] = W1[i];
    __syncthreads();
    int i = blockIdx.x * blockDim.x + threadIdx.x;
    if (i >= n) return;
    float acc[12];
    #pragma unroll
    for (int d = 0; d < 12; d++) acc[d] = 0.0f;
    const float4* xr = reinterpret_cast<const float4*>(X + (size_t)i * IND);
    #pragma unroll
    for (int k4 = 0; k4 < IND / 4; k4++) {
        float4 v = xr[k4];
        const float* w = &sW[k4 * 48];
        #pragma unroll
        for (int d = 0; d < 12; d++)
            acc[d] += v.x * w[d] + v.y * w[12 + d] + v.z * w[24 + d] + v.w * w[36 + d];
    }
    float di = g_dis[i];
    float4* hO = reinterpret_cast<float4*>(g_h1 + (size_t)i * 16);
    #pragma unroll
    for (int q = 0; q < 3; q++)
        hO[q] = make_float4(di * acc[q*4+0], di * acc[q*4+1], di * acc[q*4+2], di * acc[q*4+3]);
}

// ---------------- layer-1 gather (+ fused relu + mm2): 8 lanes per node ----------------
__global__ void __launch_bounds__(256) k_gat1(const float* __restrict__ b1,
                                              const float* __restrict__ W2, int n) {
    int gid  = blockIdx.x * blockDim.x + threadIdx.x;
    int node = gid >> 3, sub = gid & 7;
    bool valid = (node < n);
    int beg = 0, cnt = 0;
    if (valid) { beg = g_rowstart[node]; cnt = g_cnt[node]; }
    float acc[12];
    #pragma unroll
    for (int d = 0; d < 12; d++) acc[d] = 0.0f;
    #pragma unroll 2
    for (int j = sub; j < cnt; j += 8) {
        int2 e = g_csr[beg + j];
        float w = __int_as_float(e.y);
        const float4* hs = reinterpret_cast<const float4*>(g_h1 + (size_t)e.x * 16);
        float4 a = hs[0], b = hs[1], c = hs[2];
        acc[0] += w * a.x;  acc[1] += w * a.y;  acc[2]  += w * a.z;  acc[3]  += w * a.w;
        acc[4] += w * b.x;  acc[5] += w * b.y;  acc[6]  += w * b.z;  acc[7]  += w * b.w;
        acc[8] += w * c.x;  acc[9] += w * c.y;  acc[10] += w * c.z;  acc[11] += w * c.w;
    }
    #pragma unroll
    for (int d = 0; d < 12; d++) acc[d] = r8(acc[d]);
    if (valid && sub == 0) {
        float di = g_dis[node];
        const float* self = g_h1 + (size_t)node * 16;
        float o[6];
        #pragma unroll
        for (int d = 0; d < 6; d++) o[d] = 0.0f;
        #pragma unroll
        for (int k = 0; k < 12; k++) {
            float xv = fmaxf(fmaf(di, acc[k] + self[k], __ldg(&b1[k])), 0.0f);
            #pragma unroll
            for (int d = 0; d < 6; d++)
                o[d] = fmaf(xv, __ldg(&W2[k * 6 + d]), o[d]);
        }
        float4* hO = reinterpret_cast<float4*>(g_h2 + (size_t)node * 8);
        hO[0] = make_float4(di * o[0], di * o[1], di * o[2], di * o[3]);
        hO[1] = make_float4(di * o[4], di * o[5], 0.0f, 0.0f);
    }
}

// ---------------- layer-2 gather (+ fused relu + mm3): 8 lanes per node ----------------
__global__ void __launch_bounds__(256) k_gat2(const float* __restrict__ b2,
                                              const float* __restrict__ W3, int n) {
    int gid  = blockIdx.x * blockDim.x + threadIdx.x;
    int node = gid >> 3, sub = gid & 7;
    bool valid = (node < n);
    int beg = 0, cnt = 0;
    if (valid) { beg = g_rowstart[node]; cnt = g_cnt[node]; }
    float acc[6];
    #pragma unroll
    for (int d = 0; d < 6; d++) acc[d] = 0.0f;
    #pragma unroll 2
    for (int j = sub; j < cnt; j += 8) {
        int2 e = g_csr[beg + j];
        float w = __int_as_float(e.y);
        const float4* hs = reinterpret_cast<const float4*>(g_h2 + (size_t)e.x * 8);
        float4 a = hs[0], b = hs[1];
        acc[0] += w * a.x;  acc[1] += w * a.y;  acc[2] += w * a.z;
        acc[3] += w * a.w;  acc[4] += w * b.x;  acc[5] += w * b.y;
    }
    #pragma unroll
    for (int d = 0; d < 6; d++) acc[d] = r8(acc[d]);
    if (valid && sub == 0) {
        float di = g_dis[node];
        const float* self = g_h2 + (size_t)node * 8;
        float o[3] = {0.0f, 0.0f, 0.0f};
        #pragma unroll
        for (int k = 0; k < 6; k++) {
            float xv = fmaxf(fmaf(di, acc[k] + self[k], __ldg(&b2[k])), 0.0f);
            #pragma unroll
            for (int d = 0; d < 3; d++)
                o[d] = fmaf(xv, __ldg(&W3[k * 3 + d]), o[d]);
        }
        *reinterpret_cast<float4*>(g_h3 + (size_t)node * 4) =
            make_float4(di * o[0], di * o[1], di * o[2], 0.0f);
    }
}

// ---------------- layer-3 gather (+ fused relu + linear + sigmoid): 8 lanes per node ----------------
__global__ void __launch_bounds__(256) k_gat3(const float* __restrict__ b3,
                                              const float* __restrict__ Wl,
                                              const float* __restrict__ bl,
                                              float* __restrict__ out, int n) {
    int gid  = blockIdx.x * blockDim.x + threadIdx.x;
    int node = gid >> 3, sub = gid & 7;
    bool valid = (node < n);
    int beg = 0, cnt = 0;
    if (valid) { beg = g_rowstart[node]; cnt = g_cnt[node]; }
    float a0 = 0.0f, a1 = 0.0f, a2 = 0.0f;
    #pragma unroll 2
    for (int j = sub; j < cnt; j += 8) {
        int2 e = g_csr[beg + j];
        float w = __int_as_float(e.y);
        float4 h = *reinterpret_cast<const float4*>(g_h3 + (size_t)e.x * 4);
        a0 += w * h.x;  a1 += w * h.y;  a2 += w * h.z;
    }
    a0 = r8(a0);  a1 = r8(a1);  a2 = r8(a2);
    if (valid && sub == 0) {
        float di = g_dis[node];
        const float* self = g_h3 + (size_t)node * 4;
        float v0 = fmaxf(fmaf(di, a0 + self[0], __ldg(&b3[0])), 0.0f);
        float v1 = fmaxf(fmaf(di, a1 + self[1], __ldg(&b3[1])), 0.0f);
        float v2 = fmaxf(fmaf(di, a2 + self[2], __ldg(&b3[2])), 0.0f);
        float z = __ldg(&bl[0]);
        z = fmaf(v0, __ldg(&Wl[0]), z);
        z = fmaf(v1, __ldg(&Wl[1]), z);
        z = fmaf(v2, __ldg(&Wl[2]), z);
        out[node] = 1.0f / (1.0f + expf(-z));
    }
}

// ---------------- launcher ----------------
extern "C" void kernel_launch(void* const* d_in, const int* in_sizes, int n_in,
                              void* d_out, int out_size) {
    const float* X  = (const float*)d_in[0];
    const void*  EI = d_in[1];
    const float* EW = (const float*)d_in[2];
    const float* W1 = (const float*)d_in[3];
    const float* B1 = (const float*)d_in[4];
    const float* W2 = (const float*)d_in[5];
    const float* B2 = (const float*)d_in[6];
    const float* W3 = (const float*)d_in[7];
    const float* B3 = (const float*)d_in[8];
    const float* WL = (const float*)d_in[9];
    const float* BL = (const float*)d_in[10];

    int n = in_sizes[0] / IND;
    if (n > NN) n = NN;
    int E = in_sizes[2];
    if (E > NE) E = NE;

    int nb   = (n + 255) / 256;
    int eb4  = ((E + 3) / 4 + 255) / 256;
    int nb1  = (n + 1023) / 1024;           // scan blocks
    int wb8  = ((n * 8) + 255) / 256;       // 8-lane-per-node blocks

    k_detect<<<1, 32>>>((const unsigned int*)EI);
    k_zero  <<<nb, 256>>>(n);
    k_count <<<eb4, 256>>>(EI, E);
    k_scan1 <<<nb1, 256>>>(n);
    k_scan2 <<<1, 128>>>(nb1);
    k_scan3 <<<nb, 256>>>(n);
    k_place <<<eb4, 256>>>(EI, EW, E);
    k_dis   <<<nb, 256>>>(n);

    k_mm1   <<<(n + 127) / 128, 128>>>(X, W1, n);
    k_gat1  <<<wb8, 256>>>(B1, W2, n);
    k_gat2  <<<wb8, 256>>>(B2, W3, n);
    k_gat3  <<<wb8, 256>>>(B3, WL, BL, (float*)d_out, n);
}

// round 11
// speedup vs baseline: 1.3054x; 1.1045x over previous
#include <cuda_runtime.h>
#include <cuda_fp16.h>
#include <stdint.h>
#include <math.h>

#define NN  100000
#define NE  6400000
#define IND 128
#define NB1MAX 128   // max scan blocks (ceil(100000/1024)=98)

typedef unsigned int u32;

// ---------------- static device scratch (no runtime allocation) ----------------
static __device__ int   g_is64;
static __device__ int   g_cnt[NN];        // in-degree (edge count) per node
static __device__ int   g_rowstart[NN];   // exclusive prefix of g_cnt
static __device__ int   g_blksum[NB1MAX];
static __device__ int   g_blkoff[NB1MAX];
static __device__ float g_dis[NN];        // deg^{-1/2}
static __device__ int   g_rank[NE];       // per-edge rank within its dst segment
static __device__ __align__(16) __half g_h1[NN * 16]; // layer-1 h' fp16 (12 used, 32B stride)
static __device__ __align__(16) float  g_h2[NN * 8];  // layer-2 h' (6 used, 32B stride)
static __device__ __align__(16) float  g_h3[NN * 4];  // layer-3 h' (3 used, 16B stride)
static __device__ __align__(16) int2   g_csr[NE];     // (src, weight-bits) grouped by dst

// ---------------- helpers ----------------
// 8-lane xor-tree reduce (lanes grouped 0-7, 8-15, ...)
__device__ __forceinline__ float r8(float v) {
    v += __shfl_xor_sync(0xffffffffu, v, 4);
    v += __shfl_xor_sync(0xffffffffu, v, 2);
    v += __shfl_xor_sync(0xffffffffu, v, 1);
    return v;
}

// ---------------- init: zero counters + detect int64 vs int32 indices ----------------
__global__ void k_init(const u32* __restrict__ p, int n) {
    int i = blockIdx.x * blockDim.x + threadIdx.x;
    if (i < n) g_cnt[i] = 0;
    if (i == 0) {
        int is64 = 1;
        #pragma unroll
        for (int j = 0; j < 16; j++)
            if (p[2 * j + 1] != 0u) is64 = 0;
        g_is64 = is64;
    }
}

// count edges per destination AND record each edge's rank (4 edges/thread)
__global__ void k_count(const void* __restrict__ eiv, int E) {
    int e0 = (blockIdx.x * blockDim.x + threadIdx.x) * 4;
    if (e0 >= E) return;
    int d0, d1, d2, d3;
    if (e0 + 4 <= E) {
        if (g_is64) {
            const long long* base = (const long long*)eiv + E;
            longlong2 a = *(const longlong2*)(base + e0);
            longlong2 b = *(const longlong2*)(base + e0 + 2);
            d0 = (int)a.x; d1 = (int)a.y; d2 = (int)b.x; d3 = (int)b.y;
        } else {
            const int* base = (const int*)eiv + E;
            int4 a = *(const int4*)(base + e0);
            d0 = a.x; d1 = a.y; d2 = a.z; d3 = a.w;
        }
        int r0 = atomicAdd(&g_cnt[d0], 1);
        int r1 = atomicAdd(&g_cnt[d1], 1);
        int r2 = atomicAdd(&g_cnt[d2], 1);
        int r3 = atomicAdd(&g_cnt[d3], 1);
        *(int4*)(g_rank + e0) = make_int4(r0, r1, r2, r3);
    } else {
        for (int e = e0; e < E; e++) {
            int d = g_is64 ? (int)(((const long long*)eiv)[(long long)E + e])
                           : ((const int*)eiv)[E + e];
            g_rank[e] = atomicAdd(&g_cnt[d], 1);
        }
    }
}

// ---------------- 3-kernel exclusive scan of g_cnt -> g_rowstart ----------------
__global__ void k_scan1(int n) {
    __shared__ int ss[256];
    int tid = threadIdx.x;
    int base = blockIdx.x * 1024 + tid * 4;
    int c0 = (base + 0 < n) ? g_cnt[base + 0] : 0;
    int c1 = (base + 1 < n) ? g_cnt[base + 1] : 0;
    int c2 = (base + 2 < n) ? g_cnt[base + 2] : 0;
    int c3 = (base + 3 < n) ? g_cnt[base + 3] : 0;
    int s = c0 + c1 + c2 + c3;
    ss[tid] = s;
    __syncthreads();
    #pragma unroll
    for (int off = 1; off < 256; off <<= 1) {
        int v = (tid >= off) ? ss[tid - off] : 0;
        __syncthreads();
        ss[tid] += v;
        __syncthreads();
    }
    int excl = ss[tid] - s;
    if (tid == 255) g_blksum[blockIdx.x] = ss[255];
    int r = excl;
    if (base + 0 < n) g_rowstart[base + 0] = r; r += c0;
    if (base + 1 < n) g_rowstart[base + 1] = r; r += c1;
    if (base + 2 < n) g_rowstart[base + 2] = r; r += c2;
    if (base + 3 < n) g_rowstart[base + 3] = r;
}

__global__ void k_scan2(int nb1) {
    __shared__ int ss[128];
    int tid = threadIdx.x;
    int v = (tid < nb1) ? g_blksum[tid] : 0;
    ss[tid] = v;
    __syncthreads();
    #pragma unroll
    for (int off = 1; off < 128; off <<= 1) {
        int u = (tid >= off) ? ss[tid - off] : 0;
        __syncthreads();
        ss[tid] += u;
        __syncthreads();
    }
    if (tid < nb1) g_blkoff[tid] = ss[tid] - v;
}

__global__ void k_scan3(int n) {
    int i = blockIdx.x * blockDim.x + threadIdx.x;
    if (i >= n) return;
    g_rowstart[i] += g_blkoff[i >> 10];
}

// ---------------- CSR placement (no atomics): pos = rowstart[dst] + rank[e] ----------------
__device__ __forceinline__ void place1(int s, int d, float w, int r) {
    g_csr[g_rowstart[d] + r] = make_int2(s, __float_as_int(w));
}
__global__ void k_place(const void* __restrict__ eiv, const float* __restrict__ ew, int E) {
    int e0 = (blockIdx.x * blockDim.x + threadIdx.x) * 4;
    if (e0 >= E) return;
    if (e0 + 4 <= E) {
        int4   r4 = *(const int4*)(g_rank + e0);
        float4 w4 = *(const float4*)(ew + e0);
        if (g_is64) {
            const long long* sb = (const long long*)eiv;
            const long long* db = sb + E;
            longlong2 s01 = *(const longlong2*)(sb + e0);
            longlong2 s23 = *(const longlong2*)(sb + e0 + 2);
            longlong2 d01 = *(const longlong2*)(db + e0);
            longlong2 d23 = *(const longlong2*)(db + e0 + 2);
            place1((int)s01.x, (int)d01.x, w4.x, r4.x);
            place1((int)s01.y, (int)d01.y, w4.y, r4.y);
            place1((int)s23.x, (int)d23.x, w4.z, r4.z);
            place1((int)s23.y, (int)d23.y, w4.w, r4.w);
        } else {
            const int* sb = (const int*)eiv;
            const int* db = sb + E;
            int4 s4 = *(const int4*)(sb + e0);
            int4 d4 = *(const int4*)(db + e0);
            place1(s4.x, d4.x, w4.x, r4.x);
            place1(s4.y, d4.y, w4.y, r4.y);
            place1(s4.z, d4.z, w4.z, r4.z);
            place1(s4.w, d4.w, w4.w, r4.w);
        }
    } else {
        for (int e = e0; e < E; e++) {
            int s, d;
            if (g_is64) {
                s = (int)((const long long*)eiv)[e];
                d = (int)((const long long*)eiv)[(long long)E + e];
            } else {
                s = ((const int*)eiv)[e];
                d = ((const int*)eiv)[E + e];
            }
            place1(s, d, ew[e], g_rank[e]);
        }
    }
}

// ---------------- weighted degree via CSR gather -> dis (8 lanes/node) ----------------
__global__ void __launch_bounds__(256) k_deg(int n) {
    int gid  = blockIdx.x * blockDim.x + threadIdx.x;
    int node = gid >> 3, sub = gid & 7;
    bool valid = (node < n);
    int beg = 0, cnt = 0;
    if (valid) { beg = g_rowstart[node]; cnt = g_cnt[node]; }
    float s = 0.0f;
    #pragma unroll 2
    for (int j = sub; j < cnt; j += 8)
        s += __int_as_float(g_csr[beg + j].y);
    s = r8(s);
    if (valid && sub == 0) g_dis[node] = rsqrtf(1.0f + s);  // self-loop weight 1
}

// ---------------- layer 1 matmul: h1' = dis * (X @ W1) in fp16, 32B row stride ----------------
__global__ void __launch_bounds__(128) k_mm1(const float* __restrict__ X,
                                             const float* __restrict__ W1, int n) {
    __shared__ float sW[IND * 12];
    for (int i = threadIdx.x; i < IND * 12; i += blockDim.x) sW[i] = W1[i];
    __syncthreads();
    int i = blockIdx.x * blockDim.x + threadIdx.x;
    if (i >= n) return;
    float acc[12];
    #pragma unroll
    for (int d = 0; d < 12; d++) acc[d] = 0.0f;
    const float4* xr = reinterpret_cast<const float4*>(X + (size_t)i * IND);
    #pragma unroll
    for (int k4 = 0; k4 < IND / 4; k4++) {
        float4 v = xr[k4];
        const float* w = &sW[k4 * 48];
        #pragma unroll
        for (int d = 0; d < 12; d++)
            acc[d] += v.x * w[d] + v.y * w[12 + d] + v.z * w[24 + d] + v.w * w[36 + d];
    }
    float di = g_dis[i];
    u32 hp[6];
    #pragma unroll
    for (int q = 0; q < 6; q++) {
        __half2 h2v = __floats2half2_rn(di * acc[2*q], di * acc[2*q + 1]);
        hp[q] = *reinterpret_cast<u32*>(&h2v);
    }
    u32* row = reinterpret_cast<u32*>(g_h1 + (size_t)i * 16);
    *reinterpret_cast<uint4*>(row)     = make_uint4(hp[0], hp[1], hp[2], hp[3]);
    *reinterpret_cast<uint2*>(row + 4) = make_uint2(hp[4], hp[5]);
}

// ---------------- layer-1 gather (+ fused relu + mm2): 8 lanes per node ----------------
__global__ void __launch_bounds__(256) k_gat1(const float* __restrict__ b1,
                                              const float* __restrict__ W2, int n) {
    int gid  = blockIdx.x * blockDim.x + threadIdx.x;
    int node = gid >> 3, sub = gid & 7;
    bool valid = (node < n);
    int beg = 0, cnt = 0;
    if (valid) { beg = g_rowstart[node]; cnt = g_cnt[node]; }
    float acc[12];
    #pragma unroll
    for (int d = 0; d < 12; d++) acc[d] = 0.0f;
    #pragma unroll 2
    for (int j = sub; j < cnt; j += 8) {
        int2 e = g_csr[beg + j];
        float w = __int_as_float(e.y);
        const u32* row = reinterpret_cast<const u32*>(g_h1 + (size_t)e.x * 16);
        uint4 qa = *reinterpret_cast<const uint4*>(row);
        uint2 qb = *reinterpret_cast<const uint2*>(row + 4);
        float2 f0 = __half22float2(*reinterpret_cast<__half2*>(&qa.x));
        float2 f1 = __half22float2(*reinterpret_cast<__half2*>(&qa.y));
        float2 f2 = __half22float2(*reinterpret_cast<__half2*>(&qa.z));
        float2 f3 = __half22float2(*reinterpret_cast<__half2*>(&qa.w));
        float2 f4 = __half22float2(*reinterpret_cast<__half2*>(&qb.x));
        float2 f5 = __half22float2(*reinterpret_cast<__half2*>(&qb.y));
        acc[0]  += w * f0.x;  acc[1]  += w * f0.y;
        acc[2]  += w * f1.x;  acc[3]  += w * f1.y;
        acc[4]  += w * f2.x;  acc[5]  += w * f2.y;
        acc[6]  += w * f3.x;  acc[7]  += w * f3.y;
        acc[8]  += w * f4.x;  acc[9]  += w * f4.y;
        acc[10] += w * f5.x;  acc[11] += w * f5.y;
    }
    #pragma unroll
    for (int d = 0; d < 12; d++) acc[d] = r8(acc[d]);
    if (valid && sub == 0) {
        float di = g_dis[node];
        const __half* self = g_h1 + (size_t)node * 16;
        float o[6];
        #pragma unroll
        for (int d = 0; d < 6; d++) o[d] = 0.0f;
        #pragma unroll
        for (int k = 0; k < 12; k++) {
            float xv = fmaxf(fmaf(di, acc[k] + __half2float(self[k]), __ldg(&b1[k])), 0.0f);
            #pragma unroll
            for (int d = 0; d < 6; d++)
                o[d] = fmaf(xv, __ldg(&W2[k * 6 + d]), o[d]);
        }
        float4* hO = reinterpret_cast<float4*>(g_h2 + (size_t)node * 8);
        hO[0] = make_float4(di * o[0], di * o[1], di * o[2], di * o[3]);
        hO[1] = make_float4(di * o[4], di * o[5], 0.0f, 0.0f);
    }
}

// ---------------- layer-2 gather (+ fused relu + mm3): 8 lanes per node ----------------
__global__ void __launch_bounds__(256) k_gat2(const float* __restrict__ b2,
                                              const float* __restrict__ W3, int n) {
    int gid  = blockIdx.x * blockDim.x + threadIdx.x;
    int node = gid >> 3, sub = gid & 7;
    bool valid = (node < n);
    int beg = 0, cnt = 0;
    if (valid) { beg = g_rowstart[node]; cnt = g_cnt[node]; }
    float acc[6];
    #pragma unroll
    for (int d = 0; d < 6; d++) acc[d] = 0.0f;
    #pragma unroll 2
    for (int j = sub; j < cnt; j += 8) {
        int2 e = g_csr[beg + j];
        float w = __int_as_float(e.y);
        const float4* hs = reinterpret_cast<const float4*>(g_h2 + (size_t)e.x * 8);
        float4 a = hs[0], b = hs[1];
        acc[0] += w * a.x;  acc[1] += w * a.y;  acc[2] += w * a.z;
        acc[3] += w * a.w;  acc[4] += w * b.x;  acc[5] += w * b.y;
    }
    #pragma unroll
    for (int d = 0; d < 6; d++) acc[d] = r8(acc[d]);
    if (valid && sub == 0) {
        float di = g_dis[node];
        const float* self = g_h2 + (size_t)node * 8;
        float o[3] = {0.0f, 0.0f, 0.0f};
        #pragma unroll
        for (int k = 0; k < 6; k++) {
            float xv = fmaxf(fmaf(di, acc[k] + self[k], __ldg(&b2[k])), 0.0f);
            #pragma unroll
            for (int d = 0; d < 3; d++)
                o[d] = fmaf(xv, __ldg(&W3[k * 3 + d]), o[d]);
        }
        *reinterpret_cast<float4*>(g_h3 + (size_t)node * 4) =
            make_float4(di * o[0], di * o[1], di * o[2], 0.0f);
    }
}

// ---------------- layer-3 gather (+ fused relu + linear + sigmoid): 8 lanes per node ----------------
__global__ void __launch_bounds__(256) k_gat3(const float* __restrict__ b3,
                                              const float* __restrict__ Wl,
                                              const float* __restrict__ bl,
                                              float* __restrict__ out, int n) {
    int gid  = blockIdx.x * blockDim.x + threadIdx.x;
    int node = gid >> 3, sub = gid & 7;
    bool valid = (node < n);
    int beg = 0, cnt = 0;
    if (valid) { beg = g_rowstart[node]; cnt = g_cnt[node]; }
    float a0 = 0.0f, a1 = 0.0f, a2 = 0.0f;
    #pragma unroll 2
    for (int j = sub; j < cnt; j += 8) {
        int2 e = g_csr[beg + j];
        float w = __int_as_float(e.y);
        float4 h = *reinterpret_cast<const float4*>(g_h3 + (size_t)e.x * 4);
        a0 += w * h.x;  a1 += w * h.y;  a2 += w * h.z;
    }
    a0 = r8(a0);  a1 = r8(a1);  a2 = r8(a2);
    if (valid && sub == 0) {
        float di = g_dis[node];
        const float* self = g_h3 + (size_t)node * 4;
        float v0 = fmaxf(fmaf(di, a0 + self[0], __ldg(&b3[0])), 0.0f);
        float v1 = fmaxf(fmaf(di, a1 + self[1], __ldg(&b3[1])), 0.0f);
        float v2 = fmaxf(fmaf(di, a2 + self[2], __ldg(&b3[2])), 0.0f);
        float z = __ldg(&bl[0]);
        z = fmaf(v0, __ldg(&Wl[0]), z);
        z = fmaf(v1, __ldg(&Wl[1]), z);
        z = fmaf(v2, __ldg(&Wl[2]), z);
        out[node] = 1.0f / (1.0f + expf(-z));
    }
}

// ---------------- launcher ----------------
extern "C" void kernel_launch(void* const* d_in, const int* in_sizes, int n_in,
                              void* d_out, int out_size) {
    const float* X  = (const float*)d_in[0];
    const void*  EI = d_in[1];
    const float* EW = (const float*)d_in[2];
    const float* W1 = (const float*)d_in[3];
    const float* B1 = (const float*)d_in[4];
    const float* W2 = (const float*)d_in[5];
    const float* B2 = (const float*)d_in[6];
    const float* W3 = (const float*)d_in[7];
    const float* B3 = (const float*)d_in[8];
    const float* WL = (const float*)d_in[9];
    const float* BL = (const float*)d_in[10];

    int n = in_sizes[0] / IND;
    if (n > NN) n = NN;
    int E = in_sizes[2];
    if (E > NE) E = NE;

    int nb   = (n + 255) / 256;
    int eb4  = ((E + 3) / 4 + 255) / 256;
    int nb1  = (n + 1023) / 1024;           // scan blocks
    int wb8  = ((n * 8) + 255) / 256;       // 8-lane-per-node blocks

    k_init  <<<nb, 256>>>((const u32*)EI, n);
    k_count <<<eb4, 256>>>(EI, E);
    k_scan1 <<<nb1, 256>>>(n);
    k_scan2 <<<1, 128>>>(nb1);
    k_scan3 <<<nb, 256>>>(n);
    k_place <<<eb4, 256>>>(EI, EW, E);
    k_deg   <<<wb8, 256>>>(n);

    k_mm1   <<<(n + 127) / 128, 128>>>(X, W1, n);
    k_gat1  <<<wb8, 256>>>(B1, W2, n);
    k_gat2  <<<wb8, 256>>>(B2, W3, n);
    k_gat3  <<<wb8, 256>>>(B3, WL, BL, (float*)d_out, n);
}

// round 12
// speedup vs baseline: 1.3245x; 1.0146x over previous
#include <cuda_runtime.h>
#include <cuda_fp16.h>
#include <stdint.h>
#include <math.h>

#define NN  100000
#define NE  6400000
#define IND 128
#define NB1MAX 128   // max scan blocks (ceil(100000/1024)=98)

typedef unsigned int u32;

// ---------------- static device scratch (no runtime allocation) ----------------
static __device__ int   g_is64;
static __device__ int   g_cnt[NN];        // in-degree (edge count) per node
static __device__ int   g_rowstart[NN];   // exclusive prefix of g_cnt
static __device__ int   g_state[NB1MAX];  // lookback scan state: [31:30]=flag, [29:0]=value
static __device__ float g_dis[NN];        // deg^{-1/2}
static __device__ int   g_rank[NE];       // per-edge rank within its dst segment
static __device__ int   g_dst32[NE];      // int32 copy of dst (written only when is64)
static __device__ __align__(16) __half g_h1[NN * 16]; // layer-1 h' fp16 (12 used, 32B stride)
static __device__ __align__(16) float  g_h2[NN * 8];  // layer-2 h' (6 used, 32B stride)
static __device__ __align__(16) float  g_h3[NN * 4];  // layer-3 h' (3 used, 16B stride)
static __device__ __align__(16) int2   g_csr[NE];     // (src, weight-bits) grouped by dst

// ---------------- helpers ----------------
// 8-lane xor-tree reduce (lanes grouped 0-7, 8-15, ...)
__device__ __forceinline__ float r8(float v) {
    v += __shfl_xor_sync(0xffffffffu, v, 4);
    v += __shfl_xor_sync(0xffffffffu, v, 2);
    v += __shfl_xor_sync(0xffffffffu, v, 1);
    return v;
}

// ---------------- init: zero counters + scan states + detect int64 vs int32 ----------------
__global__ void k_init(const u32* __restrict__ p, int n) {
    int i = blockIdx.x * blockDim.x + threadIdx.x;
    if (i < n) g_cnt[i] = 0;
    if (i < NB1MAX) g_state[i] = 0;
    if (i == 0) {
        int is64 = 1;
        #pragma unroll
        for (int j = 0; j < 16; j++)
            if (p[2 * j + 1] != 0u) is64 = 0;
        g_is64 = is64;
    }
}

// count edges per destination AND record each edge's rank (4 edges/thread).
// For int64 input, also emit an int32 copy of dst so k_place avoids the 8B re-read.
__global__ void k_count(const void* __restrict__ eiv, int E) {
    int e0 = (blockIdx.x * blockDim.x + threadIdx.x) * 4;
    if (e0 >= E) return;
    int d0, d1, d2, d3;
    if (e0 + 4 <= E) {
        if (g_is64) {
            const long long* base = (const long long*)eiv + E;
            longlong2 a = *(const longlong2*)(base + e0);
            longlong2 b = *(const longlong2*)(base + e0 + 2);
            d0 = (int)a.x; d1 = (int)a.y; d2 = (int)b.x; d3 = (int)b.y;
            *(int4*)(g_dst32 + e0) = make_int4(d0, d1, d2, d3);
        } else {
            const int* base = (const int*)eiv + E;
            int4 a = *(const int4*)(base + e0);
            d0 = a.x; d1 = a.y; d2 = a.z; d3 = a.w;
        }
        int r0 = atomicAdd(&g_cnt[d0], 1);
        int r1 = atomicAdd(&g_cnt[d1], 1);
        int r2 = atomicAdd(&g_cnt[d2], 1);
        int r3 = atomicAdd(&g_cnt[d3], 1);
        *(int4*)(g_rank + e0) = make_int4(r0, r1, r2, r3);
    } else {
        for (int e = e0; e < E; e++) {
            int d = g_is64 ? (int)(((const long long*)eiv)[(long long)E + e])
                           : ((const int*)eiv)[E + e];
            if (g_is64) g_dst32[e] = d;
            g_rank[e] = atomicAdd(&g_cnt[d], 1);
        }
    }
}

// ---------------- single-pass exclusive scan (decoupled lookback) ----------------
// flag 0 = not ready, 1 = aggregate ready, 2 = inclusive prefix ready. value in [29:0].
__global__ void __launch_bounds__(256) k_scan(int n) {
    __shared__ int ss[256];
    __shared__ int s_prev;
    int tid = threadIdx.x, bid = blockIdx.x;
    int base = bid * 1024 + tid * 4;
    int c0 = (base + 0 < n) ? g_cnt[base + 0] : 0;
    int c1 = (base + 1 < n) ? g_cnt[base + 1] : 0;
    int c2 = (base + 2 < n) ? g_cnt[base + 2] : 0;
    int c3 = (base + 3 < n) ? g_cnt[base + 3] : 0;
    int s = c0 + c1 + c2 + c3;
    ss[tid] = s;
    __syncthreads();
    #pragma unroll
    for (int off = 1; off < 256; off <<= 1) {
        int v = (tid >= off) ? ss[tid - off] : 0;
        __syncthreads();
        ss[tid] += v;
        __syncthreads();
    }
    int lexcl = ss[tid] - s;          // local exclusive prefix within block
    if (tid == 255) {
        int T = ss[255];              // block total
        if (bid == 0) {
            atomicExch(&g_state[0], (2 << 30) | T);
            s_prev = 0;
        } else {
            atomicExch(&g_state[bid], (1 << 30) | T);
            int excl = 0;
            int p = bid - 1;
            while (p >= 0) {
                int st = atomicAdd(&g_state[p], 0);   // atomic load
                int fl = (u32)st >> 30;
                if (fl == 2) { excl += st & 0x3FFFFFFF; break; }
                if (fl == 1) { excl += st & 0x3FFFFFFF; p--; }
                // fl == 0: spin
            }
            atomicExch(&g_state[bid], (2 << 30) | (excl + T));
            s_prev = excl;
        }
    }
    __syncthreads();
    int r = s_prev + lexcl;
    if (base + 0 < n) g_rowstart[base + 0] = r; r += c0;
    if (base + 1 < n) g_rowstart[base + 1] = r; r += c1;
    if (base + 2 < n) g_rowstart[base + 2] = r; r += c2;
    if (base + 3 < n) g_rowstart[base + 3] = r;
}

// ---------------- CSR placement (no atomics): pos = rowstart[dst] + rank[e] ----------------
__device__ __forceinline__ void place1(int s, int d, float w, int r) {
    g_csr[g_rowstart[d] + r] = make_int2(s, __float_as_int(w));
}
__global__ void k_place(const void* __restrict__ eiv, const float* __restrict__ ew, int E) {
    int e0 = (blockIdx.x * blockDim.x + threadIdx.x) * 4;
    if (e0 >= E) return;
    if (e0 + 4 <= E) {
        int4   r4 = *(const int4*)(g_rank + e0);
        float4 w4 = *(const float4*)(ew + e0);
        if (g_is64) {
            const long long* sb = (const long long*)eiv;
            longlong2 s01 = *(const longlong2*)(sb + e0);
            longlong2 s23 = *(const longlong2*)(sb + e0 + 2);
            int4 d4 = *(const int4*)(g_dst32 + e0);
            place1((int)s01.x, d4.x, w4.x, r4.x);
            place1((int)s01.y, d4.y, w4.y, r4.y);
            place1((int)s23.x, d4.z, w4.z, r4.z);
            place1((int)s23.y, d4.w, w4.w, r4.w);
        } else {
            const int* sb = (const int*)eiv;
            const int* db = sb + E;
            int4 s4 = *(const int4*)(sb + e0);
            int4 d4 = *(const int4*)(db + e0);
            place1(s4.x, d4.x, w4.x, r4.x);
            place1(s4.y, d4.y, w4.y, r4.y);
            place1(s4.z, d4.z, w4.z, r4.z);
            place1(s4.w, d4.w, w4.w, r4.w);
        }
    } else {
        for (int e = e0; e < E; e++) {
            int s, d;
            if (g_is64) {
                s = (int)((const long long*)eiv)[e];
                d = g_dst32[e];
            } else {
                s = ((const int*)eiv)[e];
                d = ((const int*)eiv)[E + e];
            }
            place1(s, d, ew[e], g_rank[e]);
        }
    }
}

// ---------------- weighted degree via CSR gather -> dis (8 lanes/node) ----------------
__global__ void __launch_bounds__(256) k_deg(int n) {
    int gid  = blockIdx.x * blockDim.x + threadIdx.x;
    int node = gid >> 3, sub = gid & 7;
    bool valid = (node < n);
    int beg = 0, cnt = 0;
    if (valid) { beg = g_rowstart[node]; cnt = g_cnt[node]; }
    float s = 0.0f;
    #pragma unroll 4
    for (int j = sub; j < cnt; j += 8)
        s += __int_as_float(g_csr[beg + j].y);
    s = r8(s);
    if (valid && sub == 0) g_dis[node] = rsqrtf(1.0f + s);  // self-loop weight 1
}

// ---------------- layer 1 matmul: h1' = dis * (X @ W1) in fp16, 32B row stride ----------------
__global__ void __launch_bounds__(128) k_mm1(const float* __restrict__ X,
                                             const float* __restrict__ W1, int n) {
    __shared__ float sW[IND * 12];
    for (int i = threadIdx.x; i < IND * 12; i += blockDim.x) sW[i] = W1[i];
    __syncthreads();
    int i = blockIdx.x * blockDim.x + threadIdx.x;
    if (i >= n) return;
    float acc[12];
    #pragma unroll
    for (int d = 0; d < 12; d++) acc[d] = 0.0f;
    const float4* xr = reinterpret_cast<const float4*>(X + (size_t)i * IND);
    #pragma unroll
    for (int k4 = 0; k4 < IND / 4; k4++) {
        float4 v = xr[k4];
        const float* w = &sW[k4 * 48];
        #pragma unroll
        for (int d = 0; d < 12; d++)
            acc[d] += v.x * w[d] + v.y * w[12 + d] + v.z * w[24 + d] + v.w * w[36 + d];
    }
    float di = g_dis[i];
    u32 hp[6];
    #pragma unroll
    for (int q = 0; q < 6; q++) {
        __half2 h2v = __floats2half2_rn(di * acc[2*q], di * acc[2*q + 1]);
        hp[q] = *reinterpret_cast<u32*>(&h2v);
    }
    u32* row = reinterpret_cast<u32*>(g_h1 + (size_t)i * 16);
    *reinterpret_cast<uint4*>(row)     = make_uint4(hp[0], hp[1], hp[2], hp[3]);
    *reinterpret_cast<uint2*>(row + 4) = make_uint2(hp[4], hp[5]);
}

// ---------------- layer-1 gather (+ fused relu + mm2): 8 lanes per node ----------------
__global__ void __launch_bounds__(256) k_gat1(const float* __restrict__ b1,
                                              const float* __restrict__ W2, int n) {
    int gid  = blockIdx.x * blockDim.x + threadIdx.x;
    int node = gid >> 3, sub = gid & 7;
    bool valid = (node < n);
    int beg = 0, cnt = 0;
    if (valid) { beg = g_rowstart[node]; cnt = g_cnt[node]; }
    float acc[12];
    #pragma unroll
    for (int d = 0; d < 12; d++) acc[d] = 0.0f;
    #pragma unroll 4
    for (int j = sub; j < cnt; j += 8) {
        int2 e = g_csr[beg + j];
        float w = __int_as_float(e.y);
        const u32* row = reinterpret_cast<const u32*>(g_h1 + (size_t)e.x * 16);
        uint4 qa = *reinterpret_cast<const uint4*>(row);
        uint2 qb = *reinterpret_cast<const uint2*>(row + 4);
        float2 f0 = __half22float2(*reinterpret_cast<__half2*>(&qa.x));
        float2 f1 = __half22float2(*reinterpret_cast<__half2*>(&qa.y));
        float2 f2 = __half22float2(*reinterpret_cast<__half2*>(&qa.z));
        float2 f3 = __half22float2(*reinterpret_cast<__half2*>(&qa.w));
        float2 f4 = __half22float2(*reinterpret_cast<__half2*>(&qb.x));
        float2 f5 = __half22float2(*reinterpret_cast<__half2*>(&qb.y));
        acc[0]  += w * f0.x;  acc[1]  += w * f0.y;
        acc[2]  += w * f1.x;  acc[3]  += w * f1.y;
        acc[4]  += w * f2.x;  acc[5]  += w * f2.y;
        acc[6]  += w * f3.x;  acc[7]  += w * f3.y;
        acc[8]  += w * f4.x;  acc[9]  += w * f4.y;
        acc[10] += w * f5.x;  acc[11] += w * f5.y;
    }
    #pragma unroll
    for (int d = 0; d < 12; d++) acc[d] = r8(acc[d]);
    if (valid && sub == 0) {
        float di = g_dis[node];
        const __half* self = g_h1 + (size_t)node * 16;
        float o[6];
        #pragma unroll
        for (int d = 0; d < 6; d++) o[d] = 0.0f;
        #pragma unroll
        for (int k = 0; k < 12; k++) {
            float xv = fmaxf(fmaf(di, acc[k] + __half2float(self[k]), __ldg(&b1[k])), 0.0f);
            #pragma unroll
            for (int d = 0; d < 6; d++)
                o[d] = fmaf(xv, __ldg(&W2[k * 6 + d]), o[d]);
        }
        float4* hO = reinterpret_cast<float4*>(g_h2 + (size_t)node * 8);
        hO[0] = make_float4(di * o[0], di * o[1], di * o[2], di * o[3]);
        hO[1] = make_float4(di * o[4], di * o[5], 0.0f, 0.0f);
    }
}

// ---------------- layer-2 gather (+ fused relu + mm3): 8 lanes per node ----------------
__global__ void __launch_bounds__(256) k_gat2(const float* __restrict__ b2,
                                              const float* __restrict__ W3, int n) {
    int gid  = blockIdx.x * blockDim.x + threadIdx.x;
    int node = gid >> 3, sub = gid & 7;
    bool valid = (node < n);
    int beg = 0, cnt = 0;
    if (valid) { beg = g_rowstart[node]; cnt = g_cnt[node]; }
    float acc[6];
    #pragma unroll
    for (int d = 0; d < 6; d++) acc[d] = 0.0f;
    #pragma unroll 4
    for (int j = sub; j < cnt; j += 8) {
        int2 e = g_csr[beg + j];
        float w = __int_as_float(e.y);
        const float4* hs = reinterpret_cast<const float4*>(g_h2 + (size_t)e.x * 8);
        float4 a = hs[0], b = hs[1];
        acc[0] += w * a.x;  acc[1] += w * a.y;  acc[2] += w * a.z;
        acc[3] += w * a.w;  acc[4] += w * b.x;  acc[5] += w * b.y;
    }
    #pragma unroll
    for (int d = 0; d < 6; d++) acc[d] = r8(acc[d]);
    if (valid && sub == 0) {
        float di = g_dis[node];
        const float* self = g_h2 + (size_t)node * 8;
        float o[3] = {0.0f, 0.0f, 0.0f};
        #pragma unroll
        for (int k = 0; k < 6; k++) {
            float xv = fmaxf(fmaf(di, acc[k] + self[k], __ldg(&b2[k])), 0.0f);
            #pragma unroll
            for (int d = 0; d < 3; d++)
                o[d] = fmaf(xv, __ldg(&W3[k * 3 + d]), o[d]);
        }
        *reinterpret_cast<float4*>(g_h3 + (size_t)node * 4) =
            make_float4(di * o[0], di * o[1], di * o[2], 0.0f);
    }
}

// ---------------- layer-3 gather (+ fused relu + linear + sigmoid): 8 lanes per node ----------------
__global__ void __launch_bounds__(256) k_gat3(const float* __restrict__ b3,
                                              const float* __restrict__ Wl,
                                              const float* __restrict__ bl,
                                              float* __restrict__ out, int n) {
    int gid  = blockIdx.x * blockDim.x + threadIdx.x;
    int node = gid >> 3, sub = gid & 7;
    bool valid = (node < n);
    int beg = 0, cnt = 0;
    if (valid) { beg = g_rowstart[node]; cnt = g_cnt[node]; }
    float a0 = 0.0f, a1 = 0.0f, a2 = 0.0f;
    #pragma unroll 4
    for (int j = sub; j < cnt; j += 8) {
        int2 e = g_csr[beg + j];
        float w = __int_as_float(e.y);
        float4 h = *reinterpret_cast<const float4*>(g_h3 + (size_t)e.x * 4);
        a0 += w * h.x;  a1 += w * h.y;  a2 += w * h.z;
    }
    a0 = r8(a0);  a1 = r8(a1);  a2 = r8(a2);
    if (valid && sub == 0) {
        float di = g_dis[node];
        const float* self = g_h3 + (size_t)node * 4;
        float v0 = fmaxf(fmaf(di, a0 + self[0], __ldg(&b3[0])), 0.0f);
        float v1 = fmaxf(fmaf(di, a1 + self[1], __ldg(&b3[1])), 0.0f);
        float v2 = fmaxf(fmaf(di, a2 + self[2], __ldg(&b3[2])), 0.0f);
        float z = __ldg(&bl[0]);
        z = fmaf(v0, __ldg(&Wl[0]), z);
        z = fmaf(v1, __ldg(&Wl[1]), z);
        z = fmaf(v2, __ldg(&Wl[2]), z);
        out[node] = 1.0f / (1.0f + expf(-z));
    }
}

// ---------------- launcher ----------------
extern "C" void kernel_launch(void* const* d_in, const int* in_sizes, int n_in,
                              void* d_out, int out_size) {
    const float* X  = (const float*)d_in[0];
    const void*  EI = d_in[1];
    const float* EW = (const float*)d_in[2];
    const float* W1 = (const float*)d_in[3];
    const float* B1 = (const float*)d_in[4];
    const float* W2 = (const float*)d_in[5];
    const float* B2 = (const float*)d_in[6];
    const float* W3 = (const float*)d_in[7];
    const float* B3 = (const float*)d_in[8];
    const float* WL = (const float*)d_in[9];
    const float* BL = (const float*)d_in[10];

    int n = in_sizes[0] / IND;
    if (n > NN) n = NN;
    int E = in_sizes[2];
    if (E > NE) E = NE;

    int nb   = (n + 255) / 256;
    int eb4  = ((E + 3) / 4 + 255) / 256;
    int nb1  = (n + 1023) / 1024;           // scan blocks (<= NB1MAX, all resident)
    int wb8  = ((n * 8) + 255) / 256;       // 8-lane-per-node blocks

    k_init  <<<nb, 256>>>((const u32*)EI, n);
    k_count <<<eb4, 256>>>(EI, E);
    k_scan  <<<nb1, 256>>>(n);
    k_place <<<eb4, 256>>>(EI, EW, E);
    k_deg   <<<wb8, 256>>>(n);

    k_mm1   <<<(n + 127) / 128, 128>>>(X, W1, n);
    k_gat1  <<<wb8, 256>>>(B1, W2, n);
    k_gat2  <<<wb8, 256>>>(B2, W3, n);
    k_gat3  <<<wb8, 256>>>(B3, WL, BL, (float*)d_out, n);
}